// round 11
// baseline (speedup 1.0000x reference)
#include <cuda_runtime.h>
#include <cstdint>
#include <cstddef>

// Problem dims (fixed)
#define BB   2
#define SS   2048
#define TT   2048
#define DD   512
#define HH   8
#define DKK  64
#define FFF  2048

#define NSD  (BB*SS*DD)
#define NSF  (BB*SS*FFF)
#define AW_ELEMS ((size_t)BB*HH*(size_t)SS*TT)
#define NROWS (BB*HH*SS)              // 32768 attention rows
#define NTILE 64                      // (TT/128) tiles * 4 warp_n slots

// q,k,v,attn,ybuf,o1,o2 (7*NSD) + hh (NSF) + ebuf (AW) + psum + inv
__device__ float g_scratch[7*NSD + NSF + AW_ELEMS + (size_t)NROWS*NTILE + NROWS];

// ===========================================================================
// tf32 helpers (sm_80+ PTX — legal on plain sm_103 target)
// ===========================================================================
__device__ __forceinline__ void cvt4_tf32(uint32_t* t, float4 v){
  asm("cvt.rna.tf32.f32 %0, %1;":"=r"(t[0]):"f"(v.x));
  asm("cvt.rna.tf32.f32 %0, %1;":"=r"(t[1]):"f"(v.y));
  asm("cvt.rna.tf32.f32 %0, %1;":"=r"(t[2]):"f"(v.z));
  asm("cvt.rna.tf32.f32 %0, %1;":"=r"(t[3]):"f"(v.w));
}
__device__ __forceinline__ void mma_tf32(float* d, const uint32_t* a, const uint32_t* b){
  asm volatile(
    "mma.sync.aligned.m16n8k8.row.col.f32.tf32.tf32.f32 "
    "{%0,%1,%2,%3}, {%4,%5,%6,%7}, {%8,%9}, {%0,%1,%2,%3};"
    : "+f"(d[0]), "+f"(d[1]), "+f"(d[2]), "+f"(d[3])
    : "r"(a[0]), "r"(a[1]), "r"(a[2]), "r"(a[3]), "r"(b[0]), "r"(b[1]));
}

// ===========================================================================
// Warp-MMA tf32 GEMM (R10-proven core + fused-softmax hooks):
// C = scale*(A[M,K] @ B^T) (+bias)(+res)(relu)
//   NT=64 : warps 4m x 2n, warp tile 32x32 (MT=2)
//   NT=128: warps 2m x 4n, warp tile 64x32 (MT=4)
// BL=0: B [N,K] row-major.  BL=1: B [K,N] row-major.
// causal: 0 none; 1 skip tiles fully above diagonal; 2 limit K to row0+128.
// psum != null (logits mode): C receives e=exp(v) (masked -> exact 0);
//   deterministic per-(row, tile, warp_n) partial sums of e go to psum.
// invp != null (AV mode, BL=1): A elements are e-values; multiplied by
//   inv[row] on load (normalized aw), written to awout AND fed to the MMA.
// ===========================================================================
#define ASTRIDE 20

template<int BL, int NT>
__global__ __launch_bounds__(256) void tc_gemm(
    const float* __restrict__ A, long long sab, long long sah, int lda,
    const float* __restrict__ Bt, long long sbb, long long sbh, int ldb,
    float* __restrict__ C, long long scb, long long sch, int ldc,
    const float* __restrict__ bias,
    const float* __restrict__ res, int ldr,
    int K, float scale, int relu, int causal,
    float* __restrict__ psum, const float* __restrict__ invp,
    float* __restrict__ awout)
{
    const int row0 = blockIdx.y*128, col0 = blockIdx.x*NT;
    const int z = blockIdx.z, zb = z>>3, zh = z&7;

    constexpr int MT   = (NT==128) ? 4 : 2;
    constexpr int BCH  = NT/64;
    constexpr int BST1 = NT + 8;
    constexpr int BS_WORDS = (BL==0) ? NT*ASTRIDE : 16*BST1;

    const int tid = threadIdx.x;
    const int wid = tid>>5, lane = tid&31;
    const int warp_m = (NT==128) ? (wid>>2) : (wid>>1);
    const int warp_n = (NT==128) ? (wid&3)  : (wid&1);
    const int mbase  = warp_m * (MT*16);
    const int g = lane>>2, t4 = lane&3;

    if (causal==1 && col0 > row0+127){
        if (psum && t4 == 0){
            #pragma unroll
            for (int mt = 0; mt < MT; mt++)
                #pragma unroll
                for (int half = 0; half < 2; half++){
                    const int r = row0 + mbase + mt*16 + g + half*8;
                    psum[((size_t)z*SS + r)*NTILE + blockIdx.x*4 + warp_n] = 0.f;
                }
        }
        return;
    }
    const int Keff = (causal==2) ? (row0+128) : K;

    A  += (size_t)zb*sab + (size_t)zh*sah;
    Bt += (size_t)zb*sbb + (size_t)zh*sbh;
    C  += (size_t)zb*scb + (size_t)zh*sch;
    if (awout) awout += (size_t)zb*sab + (size_t)zh*sah;   // same geom as A

    __shared__ uint32_t As[2][128*ASTRIDE];
    __shared__ uint32_t Bs[2][BS_WORDS];

    // gmem -> smem mapping
    const int ar = tid>>1, ak = (tid&1)*8;   // A: 128 rows x 16 k
    const float* Aptr = A + (size_t)(row0+ar)*lda + ak;
    const float invr = invp ? invp[(size_t)z*SS + row0 + ar] : 0.f;

    int brow[BCH], bcol[BCH];
    const float* Bp[BCH];
    #pragma unroll
    for (int c = 0; c < BCH; c++){
        int idx = tid + c*256;
        if (BL == 0){ brow[c] = idx>>2; bcol[c] = (idx&3)*4;
                      Bp[c] = Bt + (size_t)(col0+brow[c])*ldb + bcol[c]; }
        else {
            if (NT==64){ brow[c] = idx>>4; bcol[c] = (idx&15)*4; }
            else       { brow[c] = idx>>5; bcol[c] = (idx&31)*4; }
            Bp[c] = Bt + (size_t)brow[c]*ldb + col0 + bcol[c];
        }
    }

    float4 pa0 = *(const float4*)(Aptr);
    float4 pa1 = *(const float4*)(Aptr + 4);
    float4 pb[BCH];
    #pragma unroll
    for (int c = 0; c < BCH; c++) pb[c] = *(const float4*)(Bp[c]);

    float acc[MT][4][4] = {};
    const int nIter = Keff >> 4;

    for (int i = 0; i < nIter; i++){
        const int s = i & 1;
        const int k0 = i << 4;
        { uint32_t t[4];
          if (invp){
            pa0.x*=invr; pa0.y*=invr; pa0.z*=invr; pa0.w*=invr;
            pa1.x*=invr; pa1.y*=invr; pa1.z*=invr; pa1.w*=invr;
            __stcs((float4*)&awout[(size_t)(row0+ar)*lda + k0 + ak], pa0);
            __stcs((float4*)&awout[(size_t)(row0+ar)*lda + k0 + ak + 4], pa1);
          }
          cvt4_tf32(t, pa0); *(uint4*)&As[s][ar*ASTRIDE + ak]     = *(uint4*)t;
          cvt4_tf32(t, pa1); *(uint4*)&As[s][ar*ASTRIDE + ak + 4] = *(uint4*)t;
          #pragma unroll
          for (int c = 0; c < BCH; c++){
            cvt4_tf32(t, pb[c]);
            if (BL == 0) *(uint4*)&Bs[s][brow[c]*ASTRIDE + bcol[c]] = *(uint4*)t;
            else         *(uint4*)&Bs[s][brow[c]*BST1   + bcol[c]] = *(uint4*)t;
          }
        }
        __syncthreads();
        if (i + 1 < nIter){
            pa0 = *(const float4*)(Aptr + k0 + 16);
            pa1 = *(const float4*)(Aptr + k0 + 20);
            #pragma unroll
            for (int c = 0; c < BCH; c++)
                pb[c] = (BL==0) ? *(const float4*)(Bp[c] + k0 + 16)
                                : *(const float4*)(Bp[c] + (size_t)(k0 + 16)*ldb);
        }
        #pragma unroll
        for (int ks = 0; ks < 2; ks++){
            const int kb = ks*8;
            uint32_t af[MT][4], bf[4][2];
            #pragma unroll
            for (int mt = 0; mt < MT; mt++){
                const int rA = (mbase + mt*16 + g)*ASTRIDE + kb + t4;
                af[mt][0] = As[s][rA];
                af[mt][1] = As[s][rA + 8*ASTRIDE];
                af[mt][2] = As[s][rA + 4];
                af[mt][3] = As[s][rA + 8*ASTRIDE + 4];
            }
            if (BL == 0){
                #pragma unroll
                for (int nt = 0; nt < 4; nt++){
                    const int rB = (warp_n*32 + nt*8 + g)*ASTRIDE + kb + t4;
                    bf[nt][0] = Bs[s][rB];
                    bf[nt][1] = Bs[s][rB + 4];
                }
            } else {
                #pragma unroll
                for (int nt = 0; nt < 4; nt++){
                    const int cB = warp_n*32 + nt*8 + g;
                    bf[nt][0] = Bs[s][(kb + t4)*BST1 + cB];
                    bf[nt][1] = Bs[s][(kb + t4 + 4)*BST1 + cB];
                }
            }
            #pragma unroll
            for (int mt = 0; mt < MT; mt++)
                #pragma unroll
                for (int nt = 0; nt < 4; nt++)
                    mma_tf32(acc[mt][nt], af[mt], bf[nt]);
        }
        __syncthreads();
    }

    // Epilogue. c0=(g,2t4) c1=(g,2t4+1) c2=(g+8,2t4) c3=(g+8,2t4+1).
    const bool streaming = (bias == nullptr) && (res == nullptr);
    #pragma unroll
    for (int mt = 0; mt < MT; mt++){
        #pragma unroll
        for (int half = 0; half < 2; half++){
            const int r = row0 + mbase + mt*16 + g + half*8;
            float rowsum = 0.f;
            #pragma unroll
            for (int nt = 0; nt < 4; nt++){
                const int c = col0 + warp_n*32 + nt*8 + 2*t4;
                float vx = acc[mt][nt][half*2 + 0] * scale;
                float vy = acc[mt][nt][half*2 + 1] * scale;
                float2 o;
                if (psum){
                    o.x = (causal==1 && c     > r) ? 0.f : __expf(vx);
                    o.y = (causal==1 && c + 1 > r) ? 0.f : __expf(vy);
                    rowsum += o.x + o.y;
                } else {
                    if (bias){ vx += bias[c]; vy += bias[c+1]; }
                    if (res){ const float* rp = &res[(size_t)r*ldr + c];
                              vx += rp[0]; vy += rp[1]; }
                    if (relu){ vx = fmaxf(vx, 0.f); vy = fmaxf(vy, 0.f); }
                    o.x = vx; o.y = vy;
                }
                float2* cp = (float2*)&C[(size_t)r*ldc + c];
                if (streaming) __stcs(cp, o); else *cp = o;
            }
            if (psum){
                rowsum += __shfl_xor_sync(0xffffffffu, rowsum, 1);
                rowsum += __shfl_xor_sync(0xffffffffu, rowsum, 2);
                if (t4 == 0)
                    psum[((size_t)z*SS + r)*NTILE + blockIdx.x*4 + warp_n] = rowsum;
            }
        }
    }
}

// ---------------------------------------------------------------------------
// Reduce per-row exp partial sums -> inv = 1/sum. One warp per row.
// ---------------------------------------------------------------------------
__global__ __launch_bounds__(256) void sumexp_reduce(
    const float* __restrict__ ps, float* __restrict__ inv)
{
    const int row  = blockIdx.x*8 + (threadIdx.x>>5);
    const int lane = threadIdx.x & 31;
    const float* p = ps + (size_t)row*NTILE;
    float s = p[lane] + p[lane + 32];
    #pragma unroll
    for (int o = 16; o > 0; o >>= 1) s += __shfl_xor_sync(0xffffffffu, s, o);
    if (lane == 0) inv[row] = 1.f / s;
}

// ---------------------------------------------------------------------------
// Zero-fill strictly-above-diagonal tiles of causal aw (cols >= row0+128).
// Grid (1920 rows, 16 z); within-tile masked cols handled by AV (exact 0).
// ---------------------------------------------------------------------------
__global__ __launch_bounds__(256) void zerofill_kernel(float* __restrict__ aw)
{
    const int row = blockIdx.x;            // 0..1919 (band 15 needs nothing)
    const int z   = blockIdx.y;
    const int start = (row & ~127) + 128;
    float4* p = (float4*)(aw + ((size_t)z*SS + row)*TT + start);
    const int n = (TT - start) >> 2;
    const float4 zz = make_float4(0.f,0.f,0.f,0.f);
    for (int i = threadIdx.x; i < n; i += 256) __stcs(p + i, zz);
}

// ---------------------------------------------------------------------------
// LayerNorm over D=512. One block per row, 128 threads.
// ---------------------------------------------------------------------------
__global__ __launch_bounds__(128) void ln_kernel(
    const float* __restrict__ X, const float* __restrict__ g,
    const float* __restrict__ be, float* __restrict__ O)
{
    const int tid = threadIdx.x;
    const float4* x4 = (const float4*)(X + (size_t)blockIdx.x * DD);
    float4 xv = x4[tid];
    float s  = xv.x + xv.y + xv.z + xv.w;
    float sq = xv.x*xv.x + xv.y*xv.y + xv.z*xv.z + xv.w*xv.w;
    #pragma unroll
    for (int o = 16; o > 0; o >>= 1) {
        s  += __shfl_xor_sync(0xffffffffu, s,  o);
        sq += __shfl_xor_sync(0xffffffffu, sq, o);
    }
    __shared__ float ss[4], ssq[4];
    if ((tid & 31) == 0) { ss[tid >> 5] = s; ssq[tid >> 5] = sq; }
    __syncthreads();
    s  = ss[0]  + ss[1]  + ss[2]  + ss[3];
    sq = ssq[0] + ssq[1] + ssq[2] + ssq[3];
    const float invD = 1.f / DD;
    float m = s * invD;
    float var = sq * invD - m*m;
    float rstd = rsqrtf(var + 1e-6f);
    float4 gv = ((const float4*)g)[tid];
    float4 bv = ((const float4*)be)[tid];
    float4 o;
    o.x = (xv.x - m)*rstd*gv.x + bv.x;
    o.y = (xv.y - m)*rstd*gv.y + bv.y;
    o.z = (xv.z - m)*rstd*gv.z + bv.z;
    o.w = (xv.w - m)*rstd*gv.w + bv.w;
    ((float4*)(O + (size_t)blockIdx.x * DD))[tid] = o;
}

// ===========================================================================
// Host side
// ===========================================================================
static float* scratch_ptr() {
    static float* p = nullptr;
    if (!p) cudaGetSymbolAddress((void**)&p, g_scratch);
    return p;
}

extern "C" void kernel_launch(void* const* d_in, const int* in_sizes, int n_in,
                              void* d_out, int out_size)
{
    const float* x   = (const float*)d_in[0];
    const float* enc = (const float*)d_in[1];
    const float* wq1 = (const float*)d_in[3];  const float* bq1 = (const float*)d_in[4];
    const float* wk1 = (const float*)d_in[5];  const float* bk1 = (const float*)d_in[6];
    const float* wv1 = (const float*)d_in[7];  const float* bv1 = (const float*)d_in[8];
    const float* wo1 = (const float*)d_in[9];  const float* bo1 = (const float*)d_in[10];
    const float* wq2 = (const float*)d_in[11]; const float* bq2 = (const float*)d_in[12];
    const float* wk2 = (const float*)d_in[13]; const float* bk2 = (const float*)d_in[14];
    const float* wv2 = (const float*)d_in[15]; const float* bv2 = (const float*)d_in[16];
    const float* wo2 = (const float*)d_in[17]; const float* bo2 = (const float*)d_in[18];
    const float* wf1 = (const float*)d_in[19]; const float* bf1 = (const float*)d_in[20];
    const float* wf2 = (const float*)d_in[21]; const float* bf2 = (const float*)d_in[22];
    const float* g1  = (const float*)d_in[23]; const float* be1 = (const float*)d_in[24];
    const float* g2  = (const float*)d_in[25]; const float* be2 = (const float*)d_in[26];
    const float* g3  = (const float*)d_in[27]; const float* be3 = (const float*)d_in[28];

    float* scr  = scratch_ptr();
    float* q    = scr;
    float* k    = q    + NSD;
    float* v    = k    + NSD;
    float* attn = v    + NSD;
    float* ybuf = attn + NSD;
    float* o1   = ybuf + NSD;
    float* o2   = o1   + NSD;
    float* hh   = o2   + NSD;
    float* ebuf = hh   + NSF;                       // exp(logits) scratch
    float* ps   = ebuf + AW_ELEMS;                  // partial sums
    float* invb = ps   + (size_t)NROWS*NTILE;       // 1/sum per row

    float* out3 = (float*)d_out;
    float* aw1  = out3 + NSD;
    float* aw2  = aw1  + AW_ELEMS;

    const int M  = BB*SS;                // 4096
    const long long SD = (long long)SS*DD, ST = (long long)SS*TT;
    const float* NUL = nullptr;

    #define GEMM0w(A_,sab,sah,lda, B_,sbb,sbh,ldb, C_,scb,sch,ldc, bias_,res_,ldr, Nv,Kv,Zv, sc,cz, ps_,inv_,aw_) \
        tc_gemm<0,128><<<dim3((Nv)/128,M/128*SS/M*(SS/128)/(SS/128),0), 0>>>(0)
    #undef GEMM0w

    // NT=128 for projections / logits / FFN; NT=64 for AV (N=64).
    #define G0w(A_,sab,sah,lda, B_,sbb,sbh,ldb, C_,scb,sch,ldc, bias_,res_,ldr, Mv,Nv,Kv,Zv, sc,rl,cz, ps_,inv_,aw_) \
        tc_gemm<0,128><<<dim3((Nv)/128,(Mv)/128,(Zv)), 256>>>( \
            A_,sab,sah,lda, B_,sbb,sbh,ldb, C_,scb,sch,ldc, bias_,res_,ldr, Kv,sc,rl,cz, ps_,inv_,aw_)
    #define G1w(A_,sab,sah,lda, B_,sbb,sbh,ldb, C_,scb,sch,ldc, bias_,res_,ldr, Mv,Nv,Kv,Zv, sc,rl,cz, ps_,inv_,aw_) \
        tc_gemm<1,128><<<dim3((Nv)/128,(Mv)/128,(Zv)), 256>>>( \
            A_,sab,sah,lda, B_,sbb,sbh,ldb, C_,scb,sch,ldc, bias_,res_,ldr, Kv,sc,rl,cz, ps_,inv_,aw_)
    #define G1n(A_,sab,sah,lda, B_,sbb,sbh,ldb, C_,scb,sch,ldc, bias_,res_,ldr, Mv,Nv,Kv,Zv, sc,rl,cz, ps_,inv_,aw_) \
        tc_gemm<1,64><<<dim3((Nv)/64,(Mv)/128,(Zv)), 256>>>( \
            A_,sab,sah,lda, B_,sbb,sbh,ldb, C_,scb,sch,ldc, bias_,res_,ldr, Kv,sc,rl,cz, ps_,inv_,aw_)

    // ---- self-attention (causal) ----
    G1w(x,0,0,DD,  wq1,0,0,DD,  q,0,0,DD,  bq1,NUL,0, M,DD,DD,1, 1.f,0,0, (float*)nullptr,NUL,(float*)nullptr);
    G1w(x,0,0,DD,  wk1,0,0,DD,  k,0,0,DD,  bk1,NUL,0, M,DD,DD,1, 1.f,0,0, (float*)nullptr,NUL,(float*)nullptr);
    G1w(x,0,0,DD,  wv1,0,0,DD,  v,0,0,DD,  bv1,NUL,0, M,DD,DD,1, 1.f,0,0, (float*)nullptr,NUL,(float*)nullptr);
    G0w(q,SD,64,DD,  k,SD,64,DD,  ebuf,8*ST,ST,TT, NUL,NUL,0, SS,TT,DKK,BB*HH,
        0.125f,0,1, ps,NUL,(float*)nullptr);
    sumexp_reduce<<<NROWS/8, 256>>>(ps, invb);
    zerofill_kernel<<<dim3(1920, BB*HH), 256>>>(aw1);
    G1n(ebuf,8*ST,ST,TT,  v,SD,64,DD,  attn,SD,64,DD, NUL,NUL,0, SS,DKK,TT,BB*HH,
        1.f,0,2, (float*)nullptr,invb,aw1);
    G1w(attn,0,0,DD,  wo1,0,0,DD,  ybuf,0,0,DD,  bo1,x,DD, M,DD,DD,1, 1.f,0,0, (float*)nullptr,NUL,(float*)nullptr);
    ln_kernel<<<BB*SS, 128>>>(ybuf, g1, be1, o1);

    // ---- cross-attention (no mask) ----
    G1w(o1,0,0,DD,   wq2,0,0,DD,  q,0,0,DD,  bq2,NUL,0, M,DD,DD,1, 1.f,0,0, (float*)nullptr,NUL,(float*)nullptr);
    G1w(enc,0,0,DD,  wk2,0,0,DD,  k,0,0,DD,  bk2,NUL,0, M,DD,DD,1, 1.f,0,0, (float*)nullptr,NUL,(float*)nullptr);
    G1w(enc,0,0,DD,  wv2,0,0,DD,  v,0,0,DD,  bv2,NUL,0, M,DD,DD,1, 1.f,0,0, (float*)nullptr,NUL,(float*)nullptr);
    G0w(q,SD,64,DD,  k,SD,64,DD,  ebuf,8*ST,ST,TT, NUL,NUL,0, SS,TT,DKK,BB*HH,
        0.125f,0,0, ps,NUL,(float*)nullptr);
    sumexp_reduce<<<NROWS/8, 256>>>(ps, invb);
    G1n(ebuf,8*ST,ST,TT,  v,SD,64,DD,  attn,SD,64,DD, NUL,NUL,0, SS,DKK,TT,BB*HH,
        1.f,0,0, (float*)nullptr,invb,aw2);
    G1w(attn,0,0,DD,  wo2,0,0,DD,  ybuf,0,0,DD,  bo2,o1,DD, M,DD,DD,1, 1.f,0,0, (float*)nullptr,NUL,(float*)nullptr);
    ln_kernel<<<BB*SS, 128>>>(ybuf, g2, be2, o2);

    // ---- FFN ----
    G1w(o2,0,0,DD,   wf1,0,0,FFF,  hh,0,0,FFF,  bf1,NUL,0, M,FFF,DD,1,  1.f,1,0, (float*)nullptr,NUL,(float*)nullptr);
    G1w(hh,0,0,FFF,  wf2,0,0,DD,   ybuf,0,0,DD, bf2,o2,DD, M,DD,FFF,1,  1.f,0,0, (float*)nullptr,NUL,(float*)nullptr);
    ln_kernel<<<BB*SS, 128>>>(ybuf, g3, be3, out3);
}